// round 13
// baseline (speedup 1.0000x reference)
#include <cuda_runtime.h>
#include <math.h>

// Problem constants
#define T_SEQ 2048
#define DIMM  4096
#define NH    32
#define NKV   8
#define HD    128

// Scratch (device globals: allocation-free rule)
__device__ float g_q[T_SEQ * NH * HD];     // 2048 x 4096
__device__ float g_k[T_SEQ * NKV * HD];    // 2048 x 1024
__device__ float g_v[T_SEQ * NKV * HD];    // 2048 x 1024
__device__ float g_ctx[T_SEQ * NH * HD];   // 2048 x 4096

// ---------------------------------------------------------------------------
// SGEMM: C[M,N] = A[M,K] @ B[K,N], all row-major fp32.
// BM=BN=128, BK=16, 256 threads, 8x8 per thread. All dims divide tiles.
// ---------------------------------------------------------------------------
#define BM  128
#define BN  128
#define BKK 16
#define TM  8
#define TN  8

__global__ __launch_bounds__(256)
void sgemm_kernel(const float* __restrict__ A, const float* __restrict__ B,
                  float* __restrict__ C, int M, int N, int K)
{
    __shared__ float As[BKK][BM + 4];   // A tile stored transposed (k-major)
    __shared__ float Bs[BKK][BN];

    const int tid = threadIdx.x;
    const int bm = blockIdx.y * BM;
    const int bn = blockIdx.x * BN;

    // A tile load mapping: 128 rows x 16 cols, 2 float4 per thread
    const int a_row  = tid >> 2;          // 0..63
    const int a_col4 = (tid & 3) << 2;    // 0,4,8,12
    // B tile load mapping: 16 rows x 128 cols, 2 float4 per thread
    const int b_row  = tid >> 5;          // 0..7
    const int b_col4 = (tid & 31) << 2;   // 0..124

    const int trow = (tid >> 4) * TM;     // 0..120
    const int tcol = (tid & 15) * TN;     // 0..120

    const float* Aptr = A + bm * K;
    const float* Bptr = B + bn;

    float acc[TM][TN];
    #pragma unroll
    for (int i = 0; i < TM; i++)
        #pragma unroll
        for (int j = 0; j < TN; j++) acc[i][j] = 0.f;

    for (int k0 = 0; k0 < K; k0 += BKK) {
        #pragma unroll
        for (int i = 0; i < 2; i++) {
            int r = a_row + i * 64;
            float4 av = *(const float4*)&Aptr[r * K + k0 + a_col4];
            As[a_col4 + 0][r] = av.x;
            As[a_col4 + 1][r] = av.y;
            As[a_col4 + 2][r] = av.z;
            As[a_col4 + 3][r] = av.w;
        }
        #pragma unroll
        for (int i = 0; i < 2; i++) {
            int r = b_row + i * 8;
            *(float4*)&Bs[r][b_col4] = *(const float4*)&Bptr[(k0 + r) * N + b_col4];
        }
        __syncthreads();

        #pragma unroll
        for (int kk = 0; kk < BKK; kk++) {
            float ar[TM], br[TN];
            #pragma unroll
            for (int i = 0; i < TM; i++) ar[i] = As[kk][trow + i];
            #pragma unroll
            for (int j = 0; j < TN; j++) br[j] = Bs[kk][tcol + j];
            #pragma unroll
            for (int i = 0; i < TM; i++)
                #pragma unroll
                for (int j = 0; j < TN; j++)
                    acc[i][j] = fmaf(ar[i], br[j], acc[i][j]);
        }
        __syncthreads();
    }

    #pragma unroll
    for (int i = 0; i < TM; i++) {
        #pragma unroll
        for (int j = 0; j < TN; j += 4) {
            float4 cv = make_float4(acc[i][j], acc[i][j+1], acc[i][j+2], acc[i][j+3]);
            *(float4*)&C[(bm + trow + i) * N + bn + tcol + j] = cv;
        }
    }
}

// ---------------------------------------------------------------------------
// RoPE on g_q (32 heads, with 1/sqrt(HD) score scale folded in) and g_k (8 heads).
// One thread per (t, h, pair).
// ---------------------------------------------------------------------------
__global__ void rope_kernel(const float* __restrict__ cosb, const float* __restrict__ sinb)
{
    const int NQ = T_SEQ * NH * 64;
    const int NK = T_SEQ * NKV * 64;
    int idx = blockIdx.x * blockDim.x + threadIdx.x;
    const float scale = 0.08838834764831845f;  // 1/sqrt(128)

    if (idx < NQ) {
        int i = idx & 63;
        int h = (idx >> 6) & 31;
        int t = idx >> 11;
        float* p = &g_q[(t * NH + h) * HD + 2 * i];
        float2 v = *(float2*)p;
        float c = cosb[t * 64 + i], s = sinb[t * 64 + i];
        float2 r;
        r.x = (v.x * c - v.y * s) * scale;
        r.y = (v.x * s + v.y * c) * scale;
        *(float2*)p = r;
    } else if (idx < NQ + NK) {
        int id = idx - NQ;
        int i = id & 63;
        int h = (id >> 6) & 7;
        int t = id >> 9;
        float* p = &g_k[(t * NKV + h) * HD + 2 * i];
        float2 v = *(float2*)p;
        float c = cosb[t * 64 + i], s = sinb[t * 64 + i];
        float2 r;
        r.x = v.x * c - v.y * s;
        r.y = v.x * s + v.y * c;
        *(float2*)p = r;
    }
}

// ---------------------------------------------------------------------------
// Flash attention, fp32, causal, GQA (4 Q heads per KV head).
// Grid: (T/64 q-blocks, 32 heads). Block: 256 threads.
// BR=BC=64, D=128. S: 4x4 per thread (rows ty*4.., cols tx*4..).
// O: 4x8 per thread (rows ty*4.., cols tx*8..) — same row ownership.
// ---------------------------------------------------------------------------
#define ATTN_SMEM_FLOATS (64*128 + 128*68 + 64*132 + 64*68)

__global__ __launch_bounds__(256)
void attn_kernel()
{
    extern __shared__ float sm[];
    float* Qs  = sm;                 // [64][128]
    float* Kts = Qs + 64 * 128;      // [128][68]  K transposed (d-major)
    float* Vs  = Kts + 128 * 68;     // [64][132]
    float* Ps  = Vs + 64 * 132;      // [64][68]

    const int qi = blockIdx.x;       // q tile: rows qi*64..
    const int h  = blockIdx.y;       // 0..31
    const int g  = h >> 2;           // kv head
    const int tid = threadIdx.x;
    const int tx = tid & 15;
    const int ty = tid >> 4;

    // Load Q tile (pre-scaled by rope_kernel)
    for (int i = tid; i < 2048; i += 256) {
        int r  = i >> 5;
        int c4 = (i & 31) << 2;
        *(float4*)&Qs[r * 128 + c4] =
            *(const float4*)&g_q[(qi * 64 + r) * (NH * HD) + h * HD + c4];
    }

    float m_i[4], l_i[4];
    float o_acc[4][8];
    #pragma unroll
    for (int i = 0; i < 4; i++) {
        m_i[i] = -INFINITY;
        l_i[i] = 0.f;
        #pragma unroll
        for (int j = 0; j < 8; j++) o_acc[i][j] = 0.f;
    }

    for (int j = 0; j <= qi; j++) {
        __syncthreads();  // prev iter's PV reads done before K/V overwrite; also covers Qs load
        // Load K (transposed) and V tiles for keys j*64..j*64+63
        for (int i = tid; i < 2048; i += 256) {
            int r  = i >> 5;
            int c4 = (i & 31) << 2;
            float4 kv = *(const float4*)&g_k[(j * 64 + r) * (NKV * HD) + g * HD + c4];
            Kts[(c4 + 0) * 68 + r] = kv.x;
            Kts[(c4 + 1) * 68 + r] = kv.y;
            Kts[(c4 + 2) * 68 + r] = kv.z;
            Kts[(c4 + 3) * 68 + r] = kv.w;
            *(float4*)&Vs[r * 132 + c4] =
                *(const float4*)&g_v[(j * 64 + r) * (NKV * HD) + g * HD + c4];
        }
        __syncthreads();

        // S = Q @ K^T  (Q already carries 1/sqrt(d))
        float s_acc[4][4];
        #pragma unroll
        for (int i = 0; i < 4; i++)
            #pragma unroll
            for (int jj = 0; jj < 4; jj++) s_acc[i][jj] = 0.f;

        #pragma unroll 4
        for (int kk = 0; kk < 128; kk++) {
            float4 kc = *(const float4*)&Kts[kk * 68 + tx * 4];
            #pragma unroll
            for (int i = 0; i < 4; i++) {
                float qv = Qs[(ty * 4 + i) * 128 + kk];
                s_acc[i][0] = fmaf(qv, kc.x, s_acc[i][0]);
                s_acc[i][1] = fmaf(qv, kc.y, s_acc[i][1]);
                s_acc[i][2] = fmaf(qv, kc.z, s_acc[i][2]);
                s_acc[i][3] = fmaf(qv, kc.w, s_acc[i][3]);
            }
        }

        // Causal mask on the diagonal tile
        if (j == qi) {
            #pragma unroll
            for (int i = 0; i < 4; i++)
                #pragma unroll
                for (int jj = 0; jj < 4; jj++)
                    if (tx * 4 + jj > ty * 4 + i) s_acc[i][jj] = -INFINITY;
        }

        // Online softmax update (per row; rows replicated over the 16-lane tx group)
        #pragma unroll
        for (int i = 0; i < 4; i++) {
            float rmax = fmaxf(fmaxf(s_acc[i][0], s_acc[i][1]),
                               fmaxf(s_acc[i][2], s_acc[i][3]));
            #pragma unroll
            for (int off = 8; off > 0; off >>= 1)
                rmax = fmaxf(rmax, __shfl_xor_sync(0xffffffffu, rmax, off));
            float m_new = fmaxf(m_i[i], rmax);
            float alpha = expf(m_i[i] - m_new);  // -inf - finite -> 0
            float rsum = 0.f;
            #pragma unroll
            for (int jj = 0; jj < 4; jj++) {
                float p = expf(s_acc[i][jj] - m_new);
                s_acc[i][jj] = p;
                rsum += p;
            }
            #pragma unroll
            for (int off = 8; off > 0; off >>= 1)
                rsum += __shfl_xor_sync(0xffffffffu, rsum, off);
            l_i[i] = l_i[i] * alpha + rsum;
            m_i[i] = m_new;
            #pragma unroll
            for (int jj = 0; jj < 8; jj++) o_acc[i][jj] *= alpha;
            float4 pv = make_float4(s_acc[i][0], s_acc[i][1], s_acc[i][2], s_acc[i][3]);
            *(float4*)&Ps[(ty * 4 + i) * 68 + tx * 4] = pv;
        }
        __syncthreads();

        // O += P @ V
        #pragma unroll 2
        for (int c = 0; c < 64; c++) {
            float4 v0 = *(const float4*)&Vs[c * 132 + tx * 8];
            float4 v1 = *(const float4*)&Vs[c * 132 + tx * 8 + 4];
            #pragma unroll
            for (int i = 0; i < 4; i++) {
                float p = Ps[(ty * 4 + i) * 68 + c];
                o_acc[i][0] = fmaf(p, v0.x, o_acc[i][0]);
                o_acc[i][1] = fmaf(p, v0.y, o_acc[i][1]);
                o_acc[i][2] = fmaf(p, v0.z, o_acc[i][2]);
                o_acc[i][3] = fmaf(p, v0.w, o_acc[i][3]);
                o_acc[i][4] = fmaf(p, v1.x, o_acc[i][4]);
                o_acc[i][5] = fmaf(p, v1.y, o_acc[i][5]);
                o_acc[i][6] = fmaf(p, v1.z, o_acc[i][6]);
                o_acc[i][7] = fmaf(p, v1.w, o_acc[i][7]);
            }
        }
    }

    // Epilogue: normalize and write ctx[t][h*128 + d]
    #pragma unroll
    for (int i = 0; i < 4; i++) {
        float inv = 1.f / l_i[i];
        float4 a0 = make_float4(o_acc[i][0] * inv, o_acc[i][1] * inv,
                                o_acc[i][2] * inv, o_acc[i][3] * inv);
        float4 a1 = make_float4(o_acc[i][4] * inv, o_acc[i][5] * inv,
                                o_acc[i][6] * inv, o_acc[i][7] * inv);
        int row = qi * 64 + ty * 4 + i;
        *(float4*)&g_ctx[row * (NH * HD) + h * HD + tx * 8]     = a0;
        *(float4*)&g_ctx[row * (NH * HD) + h * HD + tx * 8 + 4] = a1;
    }
}

// ---------------------------------------------------------------------------
// Launch
// ---------------------------------------------------------------------------
extern "C" void kernel_launch(void* const* d_in, const int* in_sizes, int n_in,
                              void* d_out, int out_size)
{
    const float* x  = (const float*)d_in[0];
    const float* rc = (const float*)d_in[1];
    const float* rs = (const float*)d_in[2];
    const float* wq = (const float*)d_in[3];
    const float* wk = (const float*)d_in[4];
    const float* wv = (const float*)d_in[5];
    const float* wo = (const float*)d_in[6];
    float* out = (float*)d_out;

    float *qp, *kp, *vp, *cp;
    cudaGetSymbolAddress((void**)&qp, g_q);
    cudaGetSymbolAddress((void**)&kp, g_k);
    cudaGetSymbolAddress((void**)&vp, g_v);
    cudaGetSymbolAddress((void**)&cp, g_ctx);

    const int attn_smem = ATTN_SMEM_FLOATS * (int)sizeof(float);  // 118784 B
    cudaFuncSetAttribute(attn_kernel, cudaFuncAttributeMaxDynamicSharedMemorySize, attn_smem);

    dim3 blk(256);
    // QKV projections
    sgemm_kernel<<<dim3(DIMM / BN, T_SEQ / BM), blk>>>(x, wq, qp, T_SEQ, NH * HD, DIMM);
    sgemm_kernel<<<dim3((NKV * HD) / BN, T_SEQ / BM), blk>>>(x, wk, kp, T_SEQ, NKV * HD, DIMM);
    sgemm_kernel<<<dim3((NKV * HD) / BN, T_SEQ / BM), blk>>>(x, wv, vp, T_SEQ, NKV * HD, DIMM);
    // RoPE (+ fold in 1/sqrt(d) on Q)
    int rope_threads = T_SEQ * NH * 64 + T_SEQ * NKV * 64;
    rope_kernel<<<(rope_threads + 255) / 256, 256>>>(rc, rs);
    // Causal GQA flash attention
    attn_kernel<<<dim3(T_SEQ / 64, NH), 256, attn_smem>>>();
    // Output projection -> d_out
    sgemm_kernel<<<dim3(DIMM / BN, T_SEQ / BM), blk>>>(cp, wo, out, T_SEQ, NH * HD, DIMM);
}

// round 14
// speedup vs baseline: 1.0020x; 1.0020x over previous
#include <cuda_runtime.h>
#include <math.h>

// Problem constants
#define T_SEQ 2048
#define DIMM  4096
#define NH    32
#define NKV   8
#define HD    128

// Scratch (device globals: allocation-free rule)
__device__ float g_q[T_SEQ * NH * HD];     // 2048 x 4096
__device__ float g_k[T_SEQ * NKV * HD];    // 2048 x 1024
__device__ float g_v[T_SEQ * NKV * HD];    // 2048 x 1024
__device__ float g_ctx[T_SEQ * NH * HD];   // 2048 x 4096

// ---------------------------------------------------------------------------
// SGEMM: C[M,N] = A[M,K] @ B[K,N], all row-major fp32.
// BM=BN=128, BK=16, 256 threads, 8x8 per thread. All dims divide tiles.
// ---------------------------------------------------------------------------
#define BM  128
#define BN  128
#define BKK 16
#define TM  8
#define TN  8

__global__ __launch_bounds__(256)
void sgemm_kernel(const float* __restrict__ A, const float* __restrict__ B,
                  float* __restrict__ C, int M, int N, int K)
{
    __shared__ float As[BKK][BM + 4];   // A tile stored transposed (k-major)
    __shared__ float Bs[BKK][BN];

    const int tid = threadIdx.x;
    const int bm = blockIdx.y * BM;
    const int bn = blockIdx.x * BN;

    // A tile load mapping: 128 rows x 16 cols, 2 float4 per thread
    const int a_row  = tid >> 2;          // 0..63
    const int a_col4 = (tid & 3) << 2;    // 0,4,8,12
    // B tile load mapping: 16 rows x 128 cols, 2 float4 per thread
    const int b_row  = tid >> 5;          // 0..7
    const int b_col4 = (tid & 31) << 2;   // 0..124

    const int trow = (tid >> 4) * TM;     // 0..120
    const int tcol = (tid & 15) * TN;     // 0..120

    const float* Aptr = A + bm * K;
    const float* Bptr = B + bn;

    float acc[TM][TN];
    #pragma unroll
    for (int i = 0; i < TM; i++)
        #pragma unroll
        for (int j = 0; j < TN; j++) acc[i][j] = 0.f;

    for (int k0 = 0; k0 < K; k0 += BKK) {
        #pragma unroll
        for (int i = 0; i < 2; i++) {
            int r = a_row + i * 64;
            float4 av = *(const float4*)&Aptr[r * K + k0 + a_col4];
            As[a_col4 + 0][r] = av.x;
            As[a_col4 + 1][r] = av.y;
            As[a_col4 + 2][r] = av.z;
            As[a_col4 + 3][r] = av.w;
        }
        #pragma unroll
        for (int i = 0; i < 2; i++) {
            int r = b_row + i * 8;
            *(float4*)&Bs[r][b_col4] = *(const float4*)&Bptr[(k0 + r) * N + b_col4];
        }
        __syncthreads();

        #pragma unroll
        for (int kk = 0; kk < BKK; kk++) {
            float ar[TM], br[TN];
            #pragma unroll
            for (int i = 0; i < TM; i++) ar[i] = As[kk][trow + i];
            #pragma unroll
            for (int j = 0; j < TN; j++) br[j] = Bs[kk][tcol + j];
            #pragma unroll
            for (int i = 0; i < TM; i++)
                #pragma unroll
                for (int j = 0; j < TN; j++)
                    acc[i][j] = fmaf(ar[i], br[j], acc[i][j]);
        }
        __syncthreads();
    }

    #pragma unroll
    for (int i = 0; i < TM; i++) {
        #pragma unroll
        for (int j = 0; j < TN; j += 4) {
            float4 cv = make_float4(acc[i][j], acc[i][j+1], acc[i][j+2], acc[i][j+3]);
            *(float4*)&C[(bm + trow + i) * N + bn + tcol + j] = cv;
        }
    }
}

// ---------------------------------------------------------------------------
// RoPE on g_q (32 heads, with 1/sqrt(HD) score scale folded in) and g_k (8 heads).
// One thread per (t, h, pair).
// ---------------------------------------------------------------------------
__global__ void rope_kernel(const float* __restrict__ cosb, const float* __restrict__ sinb)
{
    const int NQ = T_SEQ * NH * 64;
    const int NK = T_SEQ * NKV * 64;
    int idx = blockIdx.x * blockDim.x + threadIdx.x;
    const float scale = 0.08838834764831845f;  // 1/sqrt(128)

    if (idx < NQ) {
        int i = idx & 63;
        int h = (idx >> 6) & 31;
        int t = idx >> 11;
        float* p = &g_q[(t * NH + h) * HD + 2 * i];
        float2 v = *(float2*)p;
        float c = cosb[t * 64 + i], s = sinb[t * 64 + i];
        float2 r;
        r.x = (v.x * c - v.y * s) * scale;
        r.y = (v.x * s + v.y * c) * scale;
        *(float2*)p = r;
    } else if (idx < NQ + NK) {
        int id = idx - NQ;
        int i = id & 63;
        int h = (id >> 6) & 7;
        int t = id >> 9;
        float* p = &g_k[(t * NKV + h) * HD + 2 * i];
        float2 v = *(float2*)p;
        float c = cosb[t * 64 + i], s = sinb[t * 64 + i];
        float2 r;
        r.x = v.x * c - v.y * s;
        r.y = v.x * s + v.y * c;
        *(float2*)p = r;
    }
}

// ---------------------------------------------------------------------------
// Flash attention, fp32, causal, GQA (4 Q heads per KV head).
// Grid: (T/64 q-blocks, 32 heads). Block: 256 threads.
// BR=BC=64, D=128. S: 4x4 per thread (rows ty*4.., cols tx*4..).
// O: 4x8 per thread (rows ty*4.., cols tx*8..) — same row ownership.
// ---------------------------------------------------------------------------
#define ATTN_SMEM_FLOATS (64*128 + 128*68 + 64*132 + 64*68)

__global__ __launch_bounds__(256)
void attn_kernel()
{
    extern __shared__ float sm[];
    float* Qs  = sm;                 // [64][128]
    float* Kts = Qs + 64 * 128;      // [128][68]  K transposed (d-major)
    float* Vs  = Kts + 128 * 68;     // [64][132]
    float* Ps  = Vs + 64 * 132;      // [64][68]

    const int qi = blockIdx.x;       // q tile: rows qi*64..
    const int h  = blockIdx.y;       // 0..31
    const int g  = h >> 2;           // kv head
    const int tid = threadIdx.x;
    const int tx = tid & 15;
    const int ty = tid >> 4;

    // Load Q tile (pre-scaled by rope_kernel)
    for (int i = tid; i < 2048; i += 256) {
        int r  = i >> 5;
        int c4 = (i & 31) << 2;
        *(float4*)&Qs[r * 128 + c4] =
            *(const float4*)&g_q[(qi * 64 + r) * (NH * HD) + h * HD + c4];
    }

    float m_i[4], l_i[4];
    float o_acc[4][8];
    #pragma unroll
    for (int i = 0; i < 4; i++) {
        m_i[i] = -INFINITY;
        l_i[i] = 0.f;
        #pragma unroll
        for (int j = 0; j < 8; j++) o_acc[i][j] = 0.f;
    }

    for (int j = 0; j <= qi; j++) {
        __syncthreads();  // prev iter's PV reads done before K/V overwrite; also covers Qs load
        // Load K (transposed) and V tiles for keys j*64..j*64+63
        for (int i = tid; i < 2048; i += 256) {
            int r  = i >> 5;
            int c4 = (i & 31) << 2;
            float4 kv = *(const float4*)&g_k[(j * 64 + r) * (NKV * HD) + g * HD + c4];
            Kts[(c4 + 0) * 68 + r] = kv.x;
            Kts[(c4 + 1) * 68 + r] = kv.y;
            Kts[(c4 + 2) * 68 + r] = kv.z;
            Kts[(c4 + 3) * 68 + r] = kv.w;
            *(float4*)&Vs[r * 132 + c4] =
                *(const float4*)&g_v[(j * 64 + r) * (NKV * HD) + g * HD + c4];
        }
        __syncthreads();

        // S = Q @ K^T  (Q already carries 1/sqrt(d))
        float s_acc[4][4];
        #pragma unroll
        for (int i = 0; i < 4; i++)
            #pragma unroll
            for (int jj = 0; jj < 4; jj++) s_acc[i][jj] = 0.f;

        #pragma unroll 4
        for (int kk = 0; kk < 128; kk++) {
            float4 kc = *(const float4*)&Kts[kk * 68 + tx * 4];
            #pragma unroll
            for (int i = 0; i < 4; i++) {
                float qv = Qs[(ty * 4 + i) * 128 + kk];
                s_acc[i][0] = fmaf(qv, kc.x, s_acc[i][0]);
                s_acc[i][1] = fmaf(qv, kc.y, s_acc[i][1]);
                s_acc[i][2] = fmaf(qv, kc.z, s_acc[i][2]);
                s_acc[i][3] = fmaf(qv, kc.w, s_acc[i][3]);
            }
        }

        // Causal mask on the diagonal tile
        if (j == qi) {
            #pragma unroll
            for (int i = 0; i < 4; i++)
                #pragma unroll
                for (int jj = 0; jj < 4; jj++)
                    if (tx * 4 + jj > ty * 4 + i) s_acc[i][jj] = -INFINITY;
        }

        // Online softmax update (per row; rows replicated over the 16-lane tx group)
        #pragma unroll
        for (int i = 0; i < 4; i++) {
            float rmax = fmaxf(fmaxf(s_acc[i][0], s_acc[i][1]),
                               fmaxf(s_acc[i][2], s_acc[i][3]));
            #pragma unroll
            for (int off = 8; off > 0; off >>= 1)
                rmax = fmaxf(rmax, __shfl_xor_sync(0xffffffffu, rmax, off));
            float m_new = fmaxf(m_i[i], rmax);
            float alpha = expf(m_i[i] - m_new);  // -inf - finite -> 0
            float rsum = 0.f;
            #pragma unroll
            for (int jj = 0; jj < 4; jj++) {
                float p = expf(s_acc[i][jj] - m_new);
                s_acc[i][jj] = p;
                rsum += p;
            }
            #pragma unroll
            for (int off = 8; off > 0; off >>= 1)
                rsum += __shfl_xor_sync(0xffffffffu, rsum, off);
            l_i[i] = l_i[i] * alpha + rsum;
            m_i[i] = m_new;
            #pragma unroll
            for (int jj = 0; jj < 8; jj++) o_acc[i][jj] *= alpha;
            float4 pv = make_float4(s_acc[i][0], s_acc[i][1], s_acc[i][2], s_acc[i][3]);
            *(float4*)&Ps[(ty * 4 + i) * 68 + tx * 4] = pv;
        }
        __syncthreads();

        // O += P @ V
        #pragma unroll 2
        for (int c = 0; c < 64; c++) {
            float4 v0 = *(const float4*)&Vs[c * 132 + tx * 8];
            float4 v1 = *(const float4*)&Vs[c * 132 + tx * 8 + 4];
            #pragma unroll
            for (int i = 0; i < 4; i++) {
                float p = Ps[(ty * 4 + i) * 68 + c];
                o_acc[i][0] = fmaf(p, v0.x, o_acc[i][0]);
                o_acc[i][1] = fmaf(p, v0.y, o_acc[i][1]);
                o_acc[i][2] = fmaf(p, v0.z, o_acc[i][2]);
                o_acc[i][3] = fmaf(p, v0.w, o_acc[i][3]);
                o_acc[i][4] = fmaf(p, v1.x, o_acc[i][4]);
                o_acc[i][5] = fmaf(p, v1.y, o_acc[i][5]);
                o_acc[i][6] = fmaf(p, v1.z, o_acc[i][6]);
                o_acc[i][7] = fmaf(p, v1.w, o_acc[i][7]);
            }
        }
    }

    // Epilogue: normalize and write ctx[t][h*128 + d]
    #pragma unroll
    for (int i = 0; i < 4; i++) {
        float inv = 1.f / l_i[i];
        float4 a0 = make_float4(o_acc[i][0] * inv, o_acc[i][1] * inv,
                                o_acc[i][2] * inv, o_acc[i][3] * inv);
        float4 a1 = make_float4(o_acc[i][4] * inv, o_acc[i][5] * inv,
                                o_acc[i][6] * inv, o_acc[i][7] * inv);
        int row = qi * 64 + ty * 4 + i;
        *(float4*)&g_ctx[row * (NH * HD) + h * HD + tx * 8]     = a0;
        *(float4*)&g_ctx[row * (NH * HD) + h * HD + tx * 8 + 4] = a1;
    }
}

// ---------------------------------------------------------------------------
// Launch
// ---------------------------------------------------------------------------
extern "C" void kernel_launch(void* const* d_in, const int* in_sizes, int n_in,
                              void* d_out, int out_size)
{
    const float* x  = (const float*)d_in[0];
    const float* rc = (const float*)d_in[1];
    const float* rs = (const float*)d_in[2];
    const float* wq = (const float*)d_in[3];
    const float* wk = (const float*)d_in[4];
    const float* wv = (const float*)d_in[5];
    const float* wo = (const float*)d_in[6];
    float* out = (float*)d_out;

    float *qp, *kp, *vp, *cp;
    cudaGetSymbolAddress((void**)&qp, g_q);
    cudaGetSymbolAddress((void**)&kp, g_k);
    cudaGetSymbolAddress((void**)&vp, g_v);
    cudaGetSymbolAddress((void**)&cp, g_ctx);

    const int attn_smem = ATTN_SMEM_FLOATS * (int)sizeof(float);  // 118784 B
    cudaFuncSetAttribute(attn_kernel, cudaFuncAttributeMaxDynamicSharedMemorySize, attn_smem);

    dim3 blk(256);
    // QKV projections
    sgemm_kernel<<<dim3(DIMM / BN, T_SEQ / BM), blk>>>(x, wq, qp, T_SEQ, NH * HD, DIMM);
    sgemm_kernel<<<dim3((NKV * HD) / BN, T_SEQ / BM), blk>>>(x, wk, kp, T_SEQ, NKV * HD, DIMM);
    sgemm_kernel<<<dim3((NKV * HD) / BN, T_SEQ / BM), blk>>>(x, wv, vp, T_SEQ, NKV * HD, DIMM);
    // RoPE (+ fold in 1/sqrt(d) on Q)
    int rope_threads = T_SEQ * NH * 64 + T_SEQ * NKV * 64;
    rope_kernel<<<(rope_threads + 255) / 256, 256>>>(rc, rs);
    // Causal GQA flash attention
    attn_kernel<<<dim3(T_SEQ / 64, NH), 256, attn_smem>>>();
    // Output projection -> d_out
    sgemm_kernel<<<dim3(DIMM / BN, T_SEQ / BM), blk>>>(cp, wo, out, T_SEQ, NH * HD, DIMM);
}

// round 15
// speedup vs baseline: 1.0024x; 1.0004x over previous
#include <cuda_runtime.h>
#include <math.h>

// Problem constants
#define T_SEQ 2048
#define DIMM  4096
#define NH    32
#define NKV   8
#define HD    128

// Scratch (device globals: allocation-free rule)
__device__ float g_q[T_SEQ * NH * HD];     // 2048 x 4096
__device__ float g_k[T_SEQ * NKV * HD];    // 2048 x 1024
__device__ float g_v[T_SEQ * NKV * HD];    // 2048 x 1024
__device__ float g_ctx[T_SEQ * NH * HD];   // 2048 x 4096

// ---------------------------------------------------------------------------
// SGEMM: C[M,N] = A[M,K] @ B[K,N], all row-major fp32.
// BM=BN=128, BK=16, 256 threads, 8x8 per thread. All dims divide tiles.
// ---------------------------------------------------------------------------
#define BM  128
#define BN  128
#define BKK 16
#define TM  8
#define TN  8

__global__ __launch_bounds__(256)
void sgemm_kernel(const float* __restrict__ A, const float* __restrict__ B,
                  float* __restrict__ C, int M, int N, int K)
{
    __shared__ float As[BKK][BM + 4];   // A tile stored transposed (k-major)
    __shared__ float Bs[BKK][BN];

    const int tid = threadIdx.x;
    const int bm = blockIdx.y * BM;
    const int bn = blockIdx.x * BN;

    // A tile load mapping: 128 rows x 16 cols, 2 float4 per thread
    const int a_row  = tid >> 2;          // 0..63
    const int a_col4 = (tid & 3) << 2;    // 0,4,8,12
    // B tile load mapping: 16 rows x 128 cols, 2 float4 per thread
    const int b_row  = tid >> 5;          // 0..7
    const int b_col4 = (tid & 31) << 2;   // 0..124

    const int trow = (tid >> 4) * TM;     // 0..120
    const int tcol = (tid & 15) * TN;     // 0..120

    const float* Aptr = A + bm * K;
    const float* Bptr = B + bn;

    float acc[TM][TN];
    #pragma unroll
    for (int i = 0; i < TM; i++)
        #pragma unroll
        for (int j = 0; j < TN; j++) acc[i][j] = 0.f;

    for (int k0 = 0; k0 < K; k0 += BKK) {
        #pragma unroll
        for (int i = 0; i < 2; i++) {
            int r = a_row + i * 64;
            float4 av = *(const float4*)&Aptr[r * K + k0 + a_col4];
            As[a_col4 + 0][r] = av.x;
            As[a_col4 + 1][r] = av.y;
            As[a_col4 + 2][r] = av.z;
            As[a_col4 + 3][r] = av.w;
        }
        #pragma unroll
        for (int i = 0; i < 2; i++) {
            int r = b_row + i * 8;
            *(float4*)&Bs[r][b_col4] = *(const float4*)&Bptr[(k0 + r) * N + b_col4];
        }
        __syncthreads();

        #pragma unroll
        for (int kk = 0; kk < BKK; kk++) {
            float ar[TM], br[TN];
            #pragma unroll
            for (int i = 0; i < TM; i++) ar[i] = As[kk][trow + i];
            #pragma unroll
            for (int j = 0; j < TN; j++) br[j] = Bs[kk][tcol + j];
            #pragma unroll
            for (int i = 0; i < TM; i++)
                #pragma unroll
                for (int j = 0; j < TN; j++)
                    acc[i][j] = fmaf(ar[i], br[j], acc[i][j]);
        }
        __syncthreads();
    }

    #pragma unroll
    for (int i = 0; i < TM; i++) {
        #pragma unroll
        for (int j = 0; j < TN; j += 4) {
            float4 cv = make_float4(acc[i][j], acc[i][j+1], acc[i][j+2], acc[i][j+3]);
            *(float4*)&C[(bm + trow + i) * N + bn + tcol + j] = cv;
        }
    }
}

// ---------------------------------------------------------------------------
// RoPE on g_q (32 heads, with 1/sqrt(HD) score scale folded in) and g_k (8 heads).
// One thread per (t, h, pair).
// ---------------------------------------------------------------------------
__global__ void rope_kernel(const float* __restrict__ cosb, const float* __restrict__ sinb)
{
    const int NQ = T_SEQ * NH * 64;
    const int NK = T_SEQ * NKV * 64;
    int idx = blockIdx.x * blockDim.x + threadIdx.x;
    const float scale = 0.08838834764831845f;  // 1/sqrt(128)

    if (idx < NQ) {
        int i = idx & 63;
        int h = (idx >> 6) & 31;
        int t = idx >> 11;
        float* p = &g_q[(t * NH + h) * HD + 2 * i];
        float2 v = *(float2*)p;
        float c = cosb[t * 64 + i], s = sinb[t * 64 + i];
        float2 r;
        r.x = (v.x * c - v.y * s) * scale;
        r.y = (v.x * s + v.y * c) * scale;
        *(float2*)p = r;
    } else if (idx < NQ + NK) {
        int id = idx - NQ;
        int i = id & 63;
        int h = (id >> 6) & 7;
        int t = id >> 9;
        float* p = &g_k[(t * NKV + h) * HD + 2 * i];
        float2 v = *(float2*)p;
        float c = cosb[t * 64 + i], s = sinb[t * 64 + i];
        float2 r;
        r.x = v.x * c - v.y * s;
        r.y = v.x * s + v.y * c;
        *(float2*)p = r;
    }
}

// ---------------------------------------------------------------------------
// Flash attention, fp32, causal, GQA (4 Q heads per KV head).
// Grid: (T/64 q-blocks, 32 heads). Block: 256 threads.
// BR=BC=64, D=128. S: 4x4 per thread (rows ty*4.., cols tx*4..).
// O: 4x8 per thread (rows ty*4.., cols tx*8..) — same row ownership.
// ---------------------------------------------------------------------------
#define ATTN_SMEM_FLOATS (64*128 + 128*68 + 64*132 + 64*68)

__global__ __launch_bounds__(256)
void attn_kernel()
{
    extern __shared__ float sm[];
    float* Qs  = sm;                 // [64][128]
    float* Kts = Qs + 64 * 128;      // [128][68]  K transposed (d-major)
    float* Vs  = Kts + 128 * 68;     // [64][132]
    float* Ps  = Vs + 64 * 132;      // [64][68]

    const int qi = blockIdx.x;       // q tile: rows qi*64..
    const int h  = blockIdx.y;       // 0..31
    const int g  = h >> 2;           // kv head
    const int tid = threadIdx.x;
    const int tx = tid & 15;
    const int ty = tid >> 4;

    // Load Q tile (pre-scaled by rope_kernel)
    for (int i = tid; i < 2048; i += 256) {
        int r  = i >> 5;
        int c4 = (i & 31) << 2;
        *(float4*)&Qs[r * 128 + c4] =
            *(const float4*)&g_q[(qi * 64 + r) * (NH * HD) + h * HD + c4];
    }

    float m_i[4], l_i[4];
    float o_acc[4][8];
    #pragma unroll
    for (int i = 0; i < 4; i++) {
        m_i[i] = -INFINITY;
        l_i[i] = 0.f;
        #pragma unroll
        for (int j = 0; j < 8; j++) o_acc[i][j] = 0.f;
    }

    for (int j = 0; j <= qi; j++) {
        __syncthreads();  // prev iter's PV reads done before K/V overwrite; also covers Qs load
        // Load K (transposed) and V tiles for keys j*64..j*64+63
        for (int i = tid; i < 2048; i += 256) {
            int r  = i >> 5;
            int c4 = (i & 31) << 2;
            float4 kv = *(const float4*)&g_k[(j * 64 + r) * (NKV * HD) + g * HD + c4];
            Kts[(c4 + 0) * 68 + r] = kv.x;
            Kts[(c4 + 1) * 68 + r] = kv.y;
            Kts[(c4 + 2) * 68 + r] = kv.z;
            Kts[(c4 + 3) * 68 + r] = kv.w;
            *(float4*)&Vs[r * 132 + c4] =
                *(const float4*)&g_v[(j * 64 + r) * (NKV * HD) + g * HD + c4];
        }
        __syncthreads();

        // S = Q @ K^T  (Q already carries 1/sqrt(d))
        float s_acc[4][4];
        #pragma unroll
        for (int i = 0; i < 4; i++)
            #pragma unroll
            for (int jj = 0; jj < 4; jj++) s_acc[i][jj] = 0.f;

        #pragma unroll 4
        for (int kk = 0; kk < 128; kk++) {
            float4 kc = *(const float4*)&Kts[kk * 68 + tx * 4];
            #pragma unroll
            for (int i = 0; i < 4; i++) {
                float qv = Qs[(ty * 4 + i) * 128 + kk];
                s_acc[i][0] = fmaf(qv, kc.x, s_acc[i][0]);
                s_acc[i][1] = fmaf(qv, kc.y, s_acc[i][1]);
                s_acc[i][2] = fmaf(qv, kc.z, s_acc[i][2]);
                s_acc[i][3] = fmaf(qv, kc.w, s_acc[i][3]);
            }
        }

        // Causal mask on the diagonal tile
        if (j == qi) {
            #pragma unroll
            for (int i = 0; i < 4; i++)
                #pragma unroll
                for (int jj = 0; jj < 4; jj++)
                    if (tx * 4 + jj > ty * 4 + i) s_acc[i][jj] = -INFINITY;
        }

        // Online softmax update (per row; rows replicated over the 16-lane tx group)
        #pragma unroll
        for (int i = 0; i < 4; i++) {
            float rmax = fmaxf(fmaxf(s_acc[i][0], s_acc[i][1]),
                               fmaxf(s_acc[i][2], s_acc[i][3]));
            #pragma unroll
            for (int off = 8; off > 0; off >>= 1)
                rmax = fmaxf(rmax, __shfl_xor_sync(0xffffffffu, rmax, off));
            float m_new = fmaxf(m_i[i], rmax);
            float alpha = expf(m_i[i] - m_new);  // -inf - finite -> 0
            float rsum = 0.f;
            #pragma unroll
            for (int jj = 0; jj < 4; jj++) {
                float p = expf(s_acc[i][jj] - m_new);
                s_acc[i][jj] = p;
                rsum += p;
            }
            #pragma unroll
            for (int off = 8; off > 0; off >>= 1)
                rsum += __shfl_xor_sync(0xffffffffu, rsum, off);
            l_i[i] = l_i[i] * alpha + rsum;
            m_i[i] = m_new;
            #pragma unroll
            for (int jj = 0; jj < 8; jj++) o_acc[i][jj] *= alpha;
            float4 pv = make_float4(s_acc[i][0], s_acc[i][1], s_acc[i][2], s_acc[i][3]);
            *(float4*)&Ps[(ty * 4 + i) * 68 + tx * 4] = pv;
        }
        __syncthreads();

        // O += P @ V
        #pragma unroll 2
        for (int c = 0; c < 64; c++) {
            float4 v0 = *(const float4*)&Vs[c * 132 + tx * 8];
            float4 v1 = *(const float4*)&Vs[c * 132 + tx * 8 + 4];
            #pragma unroll
            for (int i = 0; i < 4; i++) {
                float p = Ps[(ty * 4 + i) * 68 + c];
                o_acc[i][0] = fmaf(p, v0.x, o_acc[i][0]);
                o_acc[i][1] = fmaf(p, v0.y, o_acc[i][1]);
                o_acc[i][2] = fmaf(p, v0.z, o_acc[i][2]);
                o_acc[i][3] = fmaf(p, v0.w, o_acc[i][3]);
                o_acc[i][4] = fmaf(p, v1.x, o_acc[i][4]);
                o_acc[i][5] = fmaf(p, v1.y, o_acc[i][5]);
                o_acc[i][6] = fmaf(p, v1.z, o_acc[i][6]);
                o_acc[i][7] = fmaf(p, v1.w, o_acc[i][7]);
            }
        }
    }

    // Epilogue: normalize and write ctx[t][h*128 + d]
    #pragma unroll
    for (int i = 0; i < 4; i++) {
        float inv = 1.f / l_i[i];
        float4 a0 = make_float4(o_acc[i][0] * inv, o_acc[i][1] * inv,
                                o_acc[i][2] * inv, o_acc[i][3] * inv);
        float4 a1 = make_float4(o_acc[i][4] * inv, o_acc[i][5] * inv,
                                o_acc[i][6] * inv, o_acc[i][7] * inv);
        int row = qi * 64 + ty * 4 + i;
        *(float4*)&g_ctx[row * (NH * HD) + h * HD + tx * 8]     = a0;
        *(float4*)&g_ctx[row * (NH * HD) + h * HD + tx * 8 + 4] = a1;
    }
}

// ---------------------------------------------------------------------------
// Launch
// ---------------------------------------------------------------------------
extern "C" void kernel_launch(void* const* d_in, const int* in_sizes, int n_in,
                              void* d_out, int out_size)
{
    const float* x  = (const float*)d_in[0];
    const float* rc = (const float*)d_in[1];
    const float* rs = (const float*)d_in[2];
    const float* wq = (const float*)d_in[3];
    const float* wk = (const float*)d_in[4];
    const float* wv = (const float*)d_in[5];
    const float* wo = (const float*)d_in[6];
    float* out = (float*)d_out;

    float *qp, *kp, *vp, *cp;
    cudaGetSymbolAddress((void**)&qp, g_q);
    cudaGetSymbolAddress((void**)&kp, g_k);
    cudaGetSymbolAddress((void**)&vp, g_v);
    cudaGetSymbolAddress((void**)&cp, g_ctx);

    const int attn_smem = ATTN_SMEM_FLOATS * (int)sizeof(float);  // 118784 B
    cudaFuncSetAttribute(attn_kernel, cudaFuncAttributeMaxDynamicSharedMemorySize, attn_smem);

    dim3 blk(256);
    // QKV projections
    sgemm_kernel<<<dim3(DIMM / BN, T_SEQ / BM), blk>>>(x, wq, qp, T_SEQ, NH * HD, DIMM);
    sgemm_kernel<<<dim3((NKV * HD) / BN, T_SEQ / BM), blk>>>(x, wk, kp, T_SEQ, NKV * HD, DIMM);
    sgemm_kernel<<<dim3((NKV * HD) / BN, T_SEQ / BM), blk>>>(x, wv, vp, T_SEQ, NKV * HD, DIMM);
    // RoPE (+ fold in 1/sqrt(d) on Q)
    int rope_threads = T_SEQ * NH * 64 + T_SEQ * NKV * 64;
    rope_kernel<<<(rope_threads + 255) / 256, 256>>>(rc, rs);
    // Causal GQA flash attention
    attn_kernel<<<dim3(T_SEQ / 64, NH), 256, attn_smem>>>();
    // Output projection -> d_out
    sgemm_kernel<<<dim3(DIMM / BN, T_SEQ / BM), blk>>>(cp, wo, out, T_SEQ, NH * HD, DIMM);
}

// round 16
// speedup vs baseline: 1.3249x; 1.3218x over previous
#include <cuda_runtime.h>
#include <math.h>

// Problem constants
#define T_SEQ 2048
#define DIMM  4096
#define NH    32
#define NKV   8
#define HD    128

// Scratch (device globals: allocation-free rule)
__device__ float g_q[T_SEQ * NH * HD];     // 2048 x 4096
__device__ float g_k[T_SEQ * NKV * HD];    // 2048 x 1024
__device__ float g_v[T_SEQ * NKV * HD];    // 2048 x 1024
__device__ float g_ctx[T_SEQ * NH * HD];   // 2048 x 4096

// ---------------------------------------------------------------------------
// Packed fp32x2 helpers (sm_103a FFMA2 path — exact fp32, 2x throughput)
// ---------------------------------------------------------------------------
__device__ __forceinline__ unsigned long long pk2(float x, float y) {
    unsigned long long r;
    asm("mov.b64 %0, {%1, %2};" : "=l"(r) : "f"(x), "f"(y));
    return r;
}
__device__ __forceinline__ void fma2(unsigned long long &d,
                                     unsigned long long a, unsigned long long b) {
    asm("fma.rn.f32x2 %0, %1, %2, %0;" : "+l"(d) : "l"(a), "l"(b));
}
__device__ __forceinline__ void mul2(unsigned long long &d, unsigned long long a) {
    asm("mul.rn.f32x2 %0, %0, %1;" : "+l"(d) : "l"(a));
}
__device__ __forceinline__ float2 up2(unsigned long long v) {
    float2 r;
    asm("mov.b64 {%0, %1}, %2;" : "=f"(r.x), "=f"(r.y) : "l"(v));
    return r;
}

// ---------------------------------------------------------------------------
// SGEMM: C[M,N] = A[M,K] @ B[K,N], row-major fp32, f32x2-packed accumulators.
// BM=BN=128, BK=16, 256 threads, 8x8 per thread.
// Thread columns: {tx*4..tx*4+3} and {64+tx*4..} (2-phase Bs reads).
// ---------------------------------------------------------------------------
#define BM  128
#define BN  128
#define BKK 16
#define TM  8

__device__ __forceinline__ void sgemm_body(const float* __restrict__ A,
                                           const float* __restrict__ B,
                                           float* __restrict__ C,
                                           int N, int K)
{
    __shared__ float As[BKK][BM + 4];   // A tile stored transposed (k-major)
    __shared__ float Bs[BKK][BN];

    const int tid = threadIdx.x;
    const int bm = blockIdx.y * BM;
    const int bn = blockIdx.x * BN;

    const int a_row  = tid >> 2;          // 0..63
    const int a_col4 = (tid & 3) << 2;    // 0,4,8,12
    const int b_row  = tid >> 5;          // 0..7
    const int b_col4 = (tid & 31) << 2;   // 0..124

    const int trow = (tid >> 4) * TM;     // 0..120
    const int tc0  = (tid & 15) * 4;      // 0..60 (group 0); group 1 at +64

    const float* Aptr = A + bm * K;
    const float* Bptr = B + bn;

    unsigned long long acc2[TM][4];
    #pragma unroll
    for (int i = 0; i < TM; i++)
        #pragma unroll
        for (int j = 0; j < 4; j++) acc2[i][j] = 0ull;

    for (int k0 = 0; k0 < K; k0 += BKK) {
        #pragma unroll
        for (int i = 0; i < 2; i++) {
            int r = a_row + i * 64;
            float4 av = *(const float4*)&Aptr[r * K + k0 + a_col4];
            As[a_col4 + 0][r] = av.x;
            As[a_col4 + 1][r] = av.y;
            As[a_col4 + 2][r] = av.z;
            As[a_col4 + 3][r] = av.w;
        }
        #pragma unroll
        for (int i = 0; i < 2; i++) {
            int r = b_row + i * 8;
            *(float4*)&Bs[r][b_col4] = *(const float4*)&Bptr[(k0 + r) * N + b_col4];
        }
        __syncthreads();

        #pragma unroll
        for (int kk = 0; kk < BKK; kk++) {
            float av[TM];
            *(float4*)&av[0] = *(const float4*)&As[kk][trow];
            *(float4*)&av[4] = *(const float4*)&As[kk][trow + 4];
            ulonglong2 b0 = *(const ulonglong2*)&Bs[kk][tc0];
            ulonglong2 b1 = *(const ulonglong2*)&Bs[kk][64 + tc0];
            #pragma unroll
            for (int i = 0; i < TM; i++) {
                unsigned long long ap = pk2(av[i], av[i]);
                fma2(acc2[i][0], ap, b0.x);
                fma2(acc2[i][1], ap, b0.y);
                fma2(acc2[i][2], ap, b1.x);
                fma2(acc2[i][3], ap, b1.y);
            }
        }
        __syncthreads();
    }

    #pragma unroll
    for (int i = 0; i < TM; i++) {
        float2 c0 = up2(acc2[i][0]);
        float2 c1 = up2(acc2[i][1]);
        *(float4*)&C[(bm + trow + i) * N + bn + tc0] =
            make_float4(c0.x, c0.y, c1.x, c1.y);
        c0 = up2(acc2[i][2]);
        c1 = up2(acc2[i][3]);
        *(float4*)&C[(bm + trow + i) * N + bn + 64 + tc0] =
            make_float4(c0.x, c0.y, c1.x, c1.y);
    }
}

__global__ __launch_bounds__(256, 2)
void sgemm_kernel(const float* __restrict__ A, const float* __restrict__ B,
                  float* __restrict__ C, int N, int K)
{
    sgemm_body(A, B, C, N, K);
}

// Batched K/V projection: blockIdx.z selects wk->g_k or wv->g_v.
__global__ __launch_bounds__(256, 2)
void sgemm_kv_kernel(const float* __restrict__ A,
                     const float* __restrict__ B0, const float* __restrict__ B1,
                     float* __restrict__ C0, float* __restrict__ C1)
{
    const float* B = blockIdx.z ? B1 : B0;
    float*       C = blockIdx.z ? C1 : C0;
    sgemm_body(A, B, C, NKV * HD, DIMM);
}

// ---------------------------------------------------------------------------
// RoPE on g_q (32 heads, 1/sqrt(HD) folded in) and g_k (8 heads).
// ---------------------------------------------------------------------------
__global__ void rope_kernel(const float* __restrict__ cosb, const float* __restrict__ sinb)
{
    const int NQ = T_SEQ * NH * 64;
    const int NK = T_SEQ * NKV * 64;
    int idx = blockIdx.x * blockDim.x + threadIdx.x;
    const float scale = 0.08838834764831845f;  // 1/sqrt(128)

    if (idx < NQ) {
        int i = idx & 63;
        int h = (idx >> 6) & 31;
        int t = idx >> 11;
        float* p = &g_q[(t * NH + h) * HD + 2 * i];
        float2 v = *(float2*)p;
        float c = cosb[t * 64 + i], s = sinb[t * 64 + i];
        float2 r;
        r.x = (v.x * c - v.y * s) * scale;
        r.y = (v.x * s + v.y * c) * scale;
        *(float2*)p = r;
    } else if (idx < NQ + NK) {
        int id = idx - NQ;
        int i = id & 63;
        int h = (id >> 6) & 7;
        int t = id >> 9;
        float* p = &g_k[(t * NKV + h) * HD + 2 * i];
        float2 v = *(float2*)p;
        float c = cosb[t * 64 + i], s = sinb[t * 64 + i];
        float2 r;
        r.x = v.x * c - v.y * s;
        r.y = v.x * s + v.y * c;
        *(float2*)p = r;
    }
}

// ---------------------------------------------------------------------------
// Flash attention, fp32 (f32x2-packed), causal, GQA (4 Q heads per KV head).
// Grid: (32 q-blocks, 32 heads). Block: 256 threads. BR=BC=64, D=128.
// K stored ROW-major in smem (no transpose -> no store conflicts); QK^T packs
// the reduction dim (even/odd k halves in one f32x2 accumulator).
// S cols per thread: tx+16*jj (1-phase Ps stores).
// O cols per thread: 2*tx+32*jj+{0,1} (1-phase Vs LDS.64, coalesced STG.64).
// ---------------------------------------------------------------------------
#define QKV_STRIDE 132
#define PS_STRIDE  68
#define ATTN_SMEM_FLOATS (3 * 64 * QKV_STRIDE + 64 * PS_STRIDE)

__global__ __launch_bounds__(256)
void attn_kernel()
{
    extern __shared__ float sm[];
    float* Qs = sm;                        // [64][132]
    float* Ks = Qs + 64 * QKV_STRIDE;      // [64][132] row-major
    float* Vs = Ks + 64 * QKV_STRIDE;      // [64][132]
    float* Ps = Vs + 64 * QKV_STRIDE;      // [64][68]

    const int qi = blockIdx.x;       // q tile rows qi*64..
    const int h  = blockIdx.y;       // 0..31
    const int g  = h >> 2;           // kv head
    const int tid = threadIdx.x;
    const int tx = tid & 15;
    const int ty = tid >> 4;

    // Load Q tile (pre-scaled by rope_kernel)
    for (int i = tid; i < 2048; i += 256) {
        int r  = i >> 5;
        int c4 = (i & 31) << 2;
        *(float4*)&Qs[r * QKV_STRIDE + c4] =
            *(const float4*)&g_q[(qi * 64 + r) * (NH * HD) + h * HD + c4];
    }

    float m_i[4], l_i[4];
    unsigned long long o2[4][4];
    #pragma unroll
    for (int i = 0; i < 4; i++) {
        m_i[i] = -INFINITY;
        l_i[i] = 0.f;
        #pragma unroll
        for (int j = 0; j < 4; j++) o2[i][j] = 0ull;
    }

    for (int j = 0; j <= qi; j++) {
        __syncthreads();  // prev PV reads done before K/V overwrite; covers Qs load
        // Load K and V tiles (row-major, conflict-free stores)
        for (int i = tid; i < 2048; i += 256) {
            int r  = i >> 5;
            int c4 = (i & 31) << 2;
            *(float4*)&Ks[r * QKV_STRIDE + c4] =
                *(const float4*)&g_k[(j * 64 + r) * (NKV * HD) + g * HD + c4];
            *(float4*)&Vs[r * QKV_STRIDE + c4] =
                *(const float4*)&g_v[(j * 64 + r) * (NKV * HD) + g * HD + c4];
        }
        __syncthreads();

        // S = Q @ K^T : pack along k (even/odd halves), zero dup-pack overhead
        unsigned long long s2[4][4];
        #pragma unroll
        for (int i = 0; i < 4; i++)
            #pragma unroll
            for (int jj = 0; jj < 4; jj++) s2[i][jj] = 0ull;

        #pragma unroll 4
        for (int kk = 0; kk < 128; kk += 4) {
            ulonglong2 q[4], k[4];
            #pragma unroll
            for (int i = 0; i < 4; i++)
                q[i] = *(const ulonglong2*)&Qs[(ty * 4 + i) * QKV_STRIDE + kk];
            #pragma unroll
            for (int jj = 0; jj < 4; jj++)
                k[jj] = *(const ulonglong2*)&Ks[(tx + 16 * jj) * QKV_STRIDE + kk];
            #pragma unroll
            for (int i = 0; i < 4; i++) {
                #pragma unroll
                for (int jj = 0; jj < 4; jj++) {
                    fma2(s2[i][jj], q[i].x, k[jj].x);
                    fma2(s2[i][jj], q[i].y, k[jj].y);
                }
            }
        }

        float s[4][4];
        #pragma unroll
        for (int i = 0; i < 4; i++)
            #pragma unroll
            for (int jj = 0; jj < 4; jj++) {
                float2 t = up2(s2[i][jj]);
                s[i][jj] = t.x + t.y;
            }

        // Causal mask on the diagonal tile (thread col = tx + 16*jj)
        if (j == qi) {
            #pragma unroll
            for (int i = 0; i < 4; i++)
                #pragma unroll
                for (int jj = 0; jj < 4; jj++)
                    if (tx + 16 * jj > ty * 4 + i) s[i][jj] = -INFINITY;
        }

        // Online softmax (row spread over the 16-lane tx group)
        #pragma unroll
        for (int i = 0; i < 4; i++) {
            float rmax = fmaxf(fmaxf(s[i][0], s[i][1]), fmaxf(s[i][2], s[i][3]));
            #pragma unroll
            for (int off = 8; off > 0; off >>= 1)
                rmax = fmaxf(rmax, __shfl_xor_sync(0xffffffffu, rmax, off));
            float m_new = fmaxf(m_i[i], rmax);
            float alpha = __expf(m_i[i] - m_new);  // -inf -> 0
            float rsum = 0.f;
            #pragma unroll
            for (int jj = 0; jj < 4; jj++) {
                float p = __expf(s[i][jj] - m_new);
                s[i][jj] = p;
                rsum += p;
            }
            #pragma unroll
            for (int off = 8; off > 0; off >>= 1)
                rsum += __shfl_xor_sync(0xffffffffu, rsum, off);
            l_i[i] = l_i[i] * alpha + rsum;
            m_i[i] = m_new;
            unsigned long long ap = pk2(alpha, alpha);
            #pragma unroll
            for (int jj = 0; jj < 4; jj++) mul2(o2[i][jj], ap);
            #pragma unroll
            for (int jj = 0; jj < 4; jj++)
                Ps[(ty * 4 + i) * PS_STRIDE + tx + 16 * jj] = s[i][jj];
        }
        __syncthreads();

        // O += P @ V   (o cols 2*tx + 32*jj + {0,1})
        #pragma unroll 4
        for (int c = 0; c < 64; c++) {
            unsigned long long v[4];
            #pragma unroll
            for (int jj = 0; jj < 4; jj++)
                v[jj] = *(const unsigned long long*)
                            &Vs[c * QKV_STRIDE + 2 * tx + 32 * jj];
            #pragma unroll
            for (int i = 0; i < 4; i++) {
                float p = Ps[(ty * 4 + i) * PS_STRIDE + c];
                unsigned long long pp = pk2(p, p);
                #pragma unroll
                for (int jj = 0; jj < 4; jj++) fma2(o2[i][jj], pp, v[jj]);
            }
        }
    }

    // Epilogue: normalize and write ctx[t][h*128 + d]
    #pragma unroll
    for (int i = 0; i < 4; i++) {
        float inv = 1.f / l_i[i];
        int row = qi * 64 + ty * 4 + i;
        float* dst = &g_ctx[row * (NH * HD) + h * HD];
        #pragma unroll
        for (int jj = 0; jj < 4; jj++) {
            float2 t = up2(o2[i][jj]);
            *(float2*)&dst[2 * tx + 32 * jj] = make_float2(t.x * inv, t.y * inv);
        }
    }
}

// ---------------------------------------------------------------------------
// Launch
// ---------------------------------------------------------------------------
extern "C" void kernel_launch(void* const* d_in, const int* in_sizes, int n_in,
                              void* d_out, int out_size)
{
    const float* x  = (const float*)d_in[0];
    const float* rc = (const float*)d_in[1];
    const float* rs = (const float*)d_in[2];
    const float* wq = (const float*)d_in[3];
    const float* wk = (const float*)d_in[4];
    const float* wv = (const float*)d_in[5];
    const float* wo = (const float*)d_in[6];
    float* out = (float*)d_out;

    float *qp, *kp, *vp, *cp;
    cudaGetSymbolAddress((void**)&qp, g_q);
    cudaGetSymbolAddress((void**)&kp, g_k);
    cudaGetSymbolAddress((void**)&vp, g_v);
    cudaGetSymbolAddress((void**)&cp, g_ctx);

    const int attn_smem = ATTN_SMEM_FLOATS * (int)sizeof(float);  // 118784 B
    cudaFuncSetAttribute(attn_kernel, cudaFuncAttributeMaxDynamicSharedMemorySize, attn_smem);

    dim3 blk(256);
    // Q projection
    sgemm_kernel<<<dim3(DIMM / BN, T_SEQ / BM), blk>>>(x, wq, qp, NH * HD, DIMM);
    // K + V projections (batched over z)
    sgemm_kv_kernel<<<dim3((NKV * HD) / BN, T_SEQ / BM, 2), blk>>>(x, wk, wv, kp, vp);
    // RoPE (+ fold in 1/sqrt(d) on Q)
    int rope_threads = T_SEQ * NH * 64 + T_SEQ * NKV * 64;
    rope_kernel<<<(rope_threads + 255) / 256, 256>>>(rc, rs);
    // Causal GQA flash attention
    attn_kernel<<<dim3(T_SEQ / 64, NH), 256, attn_smem>>>();
    // Output projection -> d_out
    sgemm_kernel<<<dim3(DIMM / BN, T_SEQ / BM), blk>>>(cp, wo, out, DIMM, NH * HD);
}